// round 6
// baseline (speedup 1.0000x reference)
#include <cuda_runtime.h>
#include <cuda_bf16.h>

#define BATCH  4
#define SEQ    2048
#define DMODEL 1024
#define NSTATE 16
#define SEG    32                  // segment length
#define NSEGS  (SEQ / SEG)         // 64 segments
#define NCH    (BATCH * DMODEL)    // 4096 channels

// ---------------- device scratch (static: no allocation) ----------------
__device__ float  g_c[SEG];                   // c_k = b^T A^k b
__device__ float4 g_vrev4[SEG][4];            // vrev[s] = A^{SEG-1-s} b   (float4-packed)
__device__ float4 g_Q4[SEG][4];               // Q[r]  = b^T A^{r+1}      (float4-packed)
__device__ float  g_A32[NSTATE * NSTATE];     // A^SEG
__device__ float4 g_V4[NSEGS * NCH * 4];      // injected state  [g][ch][16]   (16.8 MB)
__device__ float4 g_H4[NSEGS * NCH * 4];      // entry states    [g][ch][16]   (16.8 MB)

// ---------------- K0: precompute filter taps and transition powers ----------------
__global__ void __launch_bounds__(256) k0_precompute(const float* __restrict__ A,
                                                     const float* __restrict__ bvec) {
    __shared__ float sA[NSTATE * NSTATE];
    __shared__ float M[2][NSTATE * NSTATE];
    __shared__ float sb[NSTATE];
    const int tid = threadIdx.x;            // 256 threads
    sA[tid] = A[tid];
    if (tid < NSTATE) sb[tid] = bvec[tid];
    M[0][tid] = ((tid >> 4) == (tid & 15)) ? 1.f : 0.f;   // M = I
    __syncthreads();

    float* vrev = (float*)g_vrev4;
    float* Q    = (float*)g_Q4;

    int cur = 0;
    const int row = tid >> 4, col = tid & 15;
    for (int j = 0; j < SEG; ++j) {         // at loop top: M[cur] = A^j
        if (tid < NSTATE) {                 // vrev[SEG-1-j] = A^j b
            float a = 0.f;
            #pragma unroll
            for (int n = 0; n < NSTATE; ++n) a = fmaf(M[cur][tid * NSTATE + n], sb[n], a);
            vrev[(SEG - 1 - j) * NSTATE + tid] = a;
        } else if (tid < 32 && j >= 1) {    // Q[j-1] = b^T A^j
            const int m = tid - NSTATE;
            float a = 0.f;
            #pragma unroll
            for (int k = 0; k < NSTATE; ++k) a = fmaf(sb[k], M[cur][k * NSTATE + m], a);
            Q[(j - 1) * NSTATE + m] = a;
        }
        float a = 0.f;                      // M[1-cur] = M[cur] * A
        #pragma unroll
        for (int k = 0; k < NSTATE; ++k)
            a = fmaf(M[cur][row * NSTATE + k], sA[k * NSTATE + col], a);
        M[1 - cur][tid] = a;
        __syncthreads();
        cur ^= 1;
    }
    // M[cur] = A^SEG
    g_A32[tid] = M[cur][tid];
    if (tid < NSTATE) {                     // Q[SEG-1] = b^T A^SEG
        float a = 0.f;
        #pragma unroll
        for (int k = 0; k < NSTATE; ++k) a = fmaf(sb[k], M[cur][k * NSTATE + tid], a);
        Q[(SEG - 1) * NSTATE + tid] = a;
    }
    if (tid < SEG) {                        // c_k = b . A^k b
        float a = 0.f;
        #pragma unroll
        for (int m = 0; m < NSTATE; ++m) a = fmaf(sb[m], vrev[(SEG - 1 - tid) * NSTATE + m], a);
        g_c[tid] = a;
    }
}

// ---------------- K1: injected state only.  V = sum_s A^{SEG-1-s} b x_s ----------------
__global__ void __launch_bounds__(256) k1_inject(const float* __restrict__ x) {
    __shared__ float4 sv4[SEG][4];
    const int tid = threadIdx.x;
    if (tid < SEG * 4) ((float4*)sv4)[tid] = ((const float4*)g_vrev4)[tid];
    __syncthreads();

    const int job = blockIdx.x * 256 + tid;     // 262144 jobs = (ch, seg)
    const int d = job & (DMODEL - 1);
    const int b = (job >> 10) & 3;
    const int g = job >> 12;

    const float* xp = x + ((size_t)(b * SEQ + g * SEG)) * DMODEL + d;
    float V[NSTATE];
    #pragma unroll
    for (int m = 0; m < NSTATE; ++m) V[m] = 0.f;

    #pragma unroll
    for (int s = 0; s < SEG; ++s) {
        const float xv = xp[(size_t)s * DMODEL];
        const float4 a0 = sv4[s][0], a1 = sv4[s][1], a2 = sv4[s][2], a3 = sv4[s][3];
        V[0]  = fmaf(a0.x, xv, V[0]);  V[1]  = fmaf(a0.y, xv, V[1]);
        V[2]  = fmaf(a0.z, xv, V[2]);  V[3]  = fmaf(a0.w, xv, V[3]);
        V[4]  = fmaf(a1.x, xv, V[4]);  V[5]  = fmaf(a1.y, xv, V[5]);
        V[6]  = fmaf(a1.z, xv, V[6]);  V[7]  = fmaf(a1.w, xv, V[7]);
        V[8]  = fmaf(a2.x, xv, V[8]);  V[9]  = fmaf(a2.y, xv, V[9]);
        V[10] = fmaf(a2.z, xv, V[10]); V[11] = fmaf(a2.w, xv, V[11]);
        V[12] = fmaf(a3.x, xv, V[12]); V[13] = fmaf(a3.y, xv, V[13]);
        V[14] = fmaf(a3.z, xv, V[14]); V[15] = fmaf(a3.w, xv, V[15]);
    }
    const int ch = b * DMODEL + d;
    float4* vp = g_V4 + ((size_t)g * NCH + ch) * 4;
    vp[0] = make_float4(V[0],  V[1],  V[2],  V[3]);
    vp[1] = make_float4(V[4],  V[5],  V[6],  V[7]);
    vp[2] = make_float4(V[8],  V[9],  V[10], V[11]);
    vp[3] = make_float4(V[12], V[13], V[14], V[15]);
}

// ---------------- K2: fused sequential prefix over segments ----------------
// 16 lanes per channel (lane = state dim m). H_{g+1} = A32 H_g + V_g; store entry states.
// V double-buffered in registers so the serial chain is pure shfl+FMA.
__global__ void __launch_bounds__(256) k2_prefix(void) {
    const int tid = threadIdx.x;
    const int m   = tid & 15;
    const int ch  = (blockIdx.x * 256 + tid) >> 4;     // 256 blocks -> 4096 channels

    float ar[NSTATE];
    #pragma unroll
    for (int n = 0; n < NSTATE; ++n) ar[n] = g_A32[m * NSTATE + n];

    const float* Vs = (const float*)g_V4;
    float*       Hs = (float*)g_H4;
    const size_t off0 = (size_t)ch * NSTATE + m;
    const size_t step = (size_t)NCH * NSTATE;

    float h = 0.f;
    float v = Vs[off0];                                // prefetch g=0
    size_t off = off0;
    for (int g = 0; g < NSEGS; ++g) {
        float v_next = 0.f;
        if (g < NSEGS - 1) v_next = Vs[off + step];    // prefetch next (hides L2 latency)
        Hs[off] = h;                                   // entry state of segment g
        float a0 = v, a1 = 0.f, a2 = 0.f, a3 = 0.f;
        #pragma unroll
        for (int n = 0; n < NSTATE; n += 4) {
            a0 = fmaf(ar[n + 0], __shfl_sync(0xffffffffu, h, n + 0, 16), a0);
            a1 = fmaf(ar[n + 1], __shfl_sync(0xffffffffu, h, n + 1, 16), a1);
            a2 = fmaf(ar[n + 2], __shfl_sync(0xffffffffu, h, n + 2, 16), a2);
            a3 = fmaf(ar[n + 3], __shfl_sync(0xffffffffu, h, n + 3, 16), a3);
        }
        h = (a0 + a1) + (a2 + a3);
        v = v_next;
        off += step;
    }
}

// ---------------- K3: y = conv(x) + Q . H_seg.  2 threads per (ch,seg), x streamed ----
__global__ void __launch_bounds__(256, 4) k3_fused(const float* __restrict__ x,
                                                   float* __restrict__ out) {
    __shared__ float  sc[SEG];
    __shared__ float4 sQ4[SEG][4];
    const int tid = threadIdx.x;
    if (tid < SEG) sc[tid] = g_c[tid];
    if (tid < SEG * 4) ((float4*)sQ4)[tid] = ((const float4*)g_Q4)[tid];
    __syncthreads();

    const int job  = blockIdx.x * 256 + tid;   // 524288 jobs = (ch, seg, half)
    const int d    = job & (DMODEL - 1);
    const int b    = (job >> 10) & 3;
    const int half = (job >> 12) & 1;          // warp-uniform (bit 12)
    const int g    = job >> 13;
    const int ch   = b * DMODEL + d;

    const size_t base = ((size_t)(b * SEQ + g * SEG)) * DMODEL + d;
    const float* xp = x + base;

    // entry state H: 4x LDG.128, warp footprint 2KB contiguous
    const float4* hp = g_H4 + ((size_t)g * NCH + ch) * 4;
    const float4 h0 = hp[0], h1 = hp[1], h2 = hp[2], h3 = hp[3];

    const int rbase = half << 4;               // 0 or 16
    float acc[16];
    #pragma unroll
    for (int i = 0; i < 16; ++i) {             // acc[i] = Q[rbase+i] . H
        const float4 q0 = sQ4[rbase + i][0], q1 = sQ4[rbase + i][1];
        const float4 q2 = sQ4[rbase + i][2], q3 = sQ4[rbase + i][3];
        float a = q0.x * h0.x;
        a = fmaf(q0.y, h0.y, a); a = fmaf(q0.z, h0.z, a); a = fmaf(q0.w, h0.w, a);
        a = fmaf(q1.x, h1.x, a); a = fmaf(q1.y, h1.y, a);
        a = fmaf(q1.z, h1.z, a); a = fmaf(q1.w, h1.w, a);
        a = fmaf(q2.x, h2.x, a); a = fmaf(q2.y, h2.y, a);
        a = fmaf(q2.z, h2.z, a); a = fmaf(q2.w, h2.w, a);
        a = fmaf(q3.x, h3.x, a); a = fmaf(q3.y, h3.y, a);
        a = fmaf(q3.z, h3.z, a); a = fmaf(q3.w, h3.w, a);
        acc[i] = a;
    }

    if (half == 0) {
        // triangle: outputs r = 0..15, x streamed
        #pragma unroll
        for (int s = 0; s < 16; ++s) {
            const float xv = xp[(size_t)s * DMODEL];
            #pragma unroll
            for (int i = 0; i < 16; ++i)
                if (i >= s) acc[i] = fmaf(sc[i - s], xv, acc[i]);
        }
        float* op = out + base;
        #pragma unroll
        for (int i = 0; i < 16; ++i) op[(size_t)i * DMODEL] = acc[i];
    } else {
        // outputs r = 16..31: dense 16x16 block from old x, then triangle; x streamed
        #pragma unroll
        for (int s = 0; s < 16; ++s) {
            const float xv = xp[(size_t)s * DMODEL];
            #pragma unroll
            for (int i = 0; i < 16; ++i)
                acc[i] = fmaf(sc[16 + i - s], xv, acc[i]);
        }
        #pragma unroll
        for (int s = 16; s < 32; ++s) {
            const float xv = xp[(size_t)s * DMODEL];
            #pragma unroll
            for (int i = 0; i < 16; ++i)
                if (16 + i >= s) acc[i] = fmaf(sc[16 + i - s], xv, acc[i]);
        }
        float* op = out + base + (size_t)16 * DMODEL;
        #pragma unroll
        for (int i = 0; i < 16; ++i) op[(size_t)i * DMODEL] = acc[i];
    }
}

// ---------------- launch ----------------
extern "C" void kernel_launch(void* const* d_in, const int* in_sizes, int n_in,
                              void* d_out, int out_size) {
    const float* x = nullptr; const float* A = nullptr; const float* bv = nullptr;
    for (int i = 0; i < n_in; ++i) {
        if      (in_sizes[i] == BATCH * SEQ * DMODEL) x  = (const float*)d_in[i];
        else if (in_sizes[i] == NSTATE * NSTATE)      A  = (const float*)d_in[i];
        else if (in_sizes[i] == NSTATE)               bv = (const float*)d_in[i];
    }
    float* out = (float*)d_out;

    k0_precompute<<<1, 256>>>(A, bv);
    k1_inject<<<(NCH * NSEGS) / 256, 256>>>(x);              // 1024 blocks
    k2_prefix<<<(NCH * NSTATE) / 256, 256>>>();              // 256 blocks
    k3_fused<<<(NCH * NSEGS * 2) / 256, 256>>>(x, out);      // 2048 blocks
}

// round 7
// speedup vs baseline: 1.0319x; 1.0319x over previous
#include <cuda_runtime.h>
#include <cuda_bf16.h>

#define BATCH  4
#define SEQ    2048
#define DMODEL 1024
#define NSTATE 16
#define SEG    32                  // segment length
#define NSEGS  (SEQ / SEG)         // 64 segments
#define NCH    (BATCH * DMODEL)    // 4096 channels

typedef unsigned long long ull;

// packed f32x2 helpers (true fp32 lanes — no precision loss)
__device__ __forceinline__ ull pack2(float lo, float hi) {
    ull r; asm("mov.b64 %0, {%1, %2};" : "=l"(r) : "f"(lo), "f"(hi)); return r;
}
__device__ __forceinline__ void fma2(ull& d, ull a, ull b) {
    asm("fma.rn.f32x2 %0, %1, %2, %0;" : "+l"(d) : "l"(a), "l"(b));
}
__device__ __forceinline__ float unpack_add(ull p) {
    float lo, hi; asm("mov.b64 {%0, %1}, %2;" : "=f"(lo), "=f"(hi) : "l"(p));
    return lo + hi;
}

// ---------------- device scratch (static: no allocation) ----------------
__device__ float  g_c[SEG];                   // c_k = b^T A^k b
__device__ float4 g_vrev4[SEG][4];            // vrev[s] = A^{SEG-1-s} b   (float4-packed)
__device__ float4 g_Q4[SEG][4];               // Q[r]  = b^T A^{r+1}      (float4-packed)
__device__ float  g_A32[NSTATE * NSTATE];     // A^SEG
__device__ float4 g_V4[NSEGS * NCH * 4];      // injected state  [g][ch][16]   (16.8 MB)
__device__ float4 g_H4[NSEGS * NCH * 4];      // entry states    [g][ch][16]   (16.8 MB)

// ---------------- K0: precompute filter taps and transition powers ----------------
__global__ void __launch_bounds__(256) k0_precompute(const float* __restrict__ A,
                                                     const float* __restrict__ bvec) {
    __shared__ float sA[NSTATE * NSTATE];
    __shared__ float M[2][NSTATE * NSTATE];
    __shared__ float sb[NSTATE];
    const int tid = threadIdx.x;            // 256 threads
    sA[tid] = A[tid];
    if (tid < NSTATE) sb[tid] = bvec[tid];
    M[0][tid] = ((tid >> 4) == (tid & 15)) ? 1.f : 0.f;   // M = I
    __syncthreads();

    float* vrev = (float*)g_vrev4;
    float* Q    = (float*)g_Q4;

    int cur = 0;
    const int row = tid >> 4, col = tid & 15;
    for (int j = 0; j < SEG; ++j) {         // at loop top: M[cur] = A^j
        if (tid < NSTATE) {                 // vrev[SEG-1-j] = A^j b
            float a = 0.f;
            #pragma unroll
            for (int n = 0; n < NSTATE; ++n) a = fmaf(M[cur][tid * NSTATE + n], sb[n], a);
            vrev[(SEG - 1 - j) * NSTATE + tid] = a;
        } else if (tid < 32 && j >= 1) {    // Q[j-1] = b^T A^j
            const int m = tid - NSTATE;
            float a = 0.f;
            #pragma unroll
            for (int k = 0; k < NSTATE; ++k) a = fmaf(sb[k], M[cur][k * NSTATE + m], a);
            Q[(j - 1) * NSTATE + m] = a;
        }
        float a = 0.f;                      // M[1-cur] = M[cur] * A
        #pragma unroll
        for (int k = 0; k < NSTATE; ++k)
            a = fmaf(M[cur][row * NSTATE + k], sA[k * NSTATE + col], a);
        M[1 - cur][tid] = a;
        __syncthreads();
        cur ^= 1;
    }
    // M[cur] = A^SEG
    g_A32[tid] = M[cur][tid];
    if (tid < NSTATE) {                     // Q[SEG-1] = b^T A^SEG
        float a = 0.f;
        #pragma unroll
        for (int k = 0; k < NSTATE; ++k) a = fmaf(sb[k], M[cur][k * NSTATE + tid], a);
        Q[(SEG - 1) * NSTATE + tid] = a;
    }
    if (tid < SEG) {                        // c_k = b . A^k b
        float a = 0.f;
        #pragma unroll
        for (int m = 0; m < NSTATE; ++m) a = fmaf(sb[m], vrev[(SEG - 1 - tid) * NSTATE + m], a);
        g_c[tid] = a;
    }
}

// ---------------- K1: injected state.  V = sum_s A^{SEG-1-s} b x_s  (packed f32x2) ----
__global__ void __launch_bounds__(256) k1_inject(const float* __restrict__ x) {
    __shared__ ulonglong2 sv2[SEG][4];      // vrev rows as 8 packed f32x2 pairs each
    const int tid = threadIdx.x;
    if (tid < SEG * 4) ((ulonglong2*)sv2)[tid] = ((const ulonglong2*)g_vrev4)[tid];
    __syncthreads();

    const int job = blockIdx.x * 256 + tid;     // 262144 jobs = (ch, seg)
    const int d = job & (DMODEL - 1);
    const int b = (job >> 10) & 3;
    const int g = job >> 12;

    const float* xp = x + ((size_t)(b * SEQ + g * SEG)) * DMODEL + d;
    ull V2[8];
    #pragma unroll
    for (int j = 0; j < 8; ++j) V2[j] = 0ull;

    #pragma unroll
    for (int s = 0; s < SEG; ++s) {
        const float xv  = xp[(size_t)s * DMODEL];
        const ull   xv2 = pack2(xv, xv);
        const ulonglong2 p0 = sv2[s][0], p1 = sv2[s][1], p2 = sv2[s][2], p3 = sv2[s][3];
        fma2(V2[0], p0.x, xv2); fma2(V2[1], p0.y, xv2);
        fma2(V2[2], p1.x, xv2); fma2(V2[3], p1.y, xv2);
        fma2(V2[4], p2.x, xv2); fma2(V2[5], p2.y, xv2);
        fma2(V2[6], p3.x, xv2); fma2(V2[7], p3.y, xv2);
    }
    const int ch = b * DMODEL + d;
    ulonglong2* vp = (ulonglong2*)(g_V4 + ((size_t)g * NCH + ch) * 4);
    vp[0] = make_ulonglong2(V2[0], V2[1]);
    vp[1] = make_ulonglong2(V2[2], V2[3]);
    vp[2] = make_ulonglong2(V2[4], V2[5]);
    vp[3] = make_ulonglong2(V2[6], V2[7]);
}

// ---------------- K2: fused sequential prefix over segments ----------------
// 16 lanes per channel (lane = state dim m). H_{g+1} = A32 H_g + V_g; store entry states.
__global__ void __launch_bounds__(256) k2_prefix(void) {
    const int tid = threadIdx.x;
    const int m   = tid & 15;
    const int ch  = (blockIdx.x * 256 + tid) >> 4;     // 256 blocks -> 4096 channels

    float ar[NSTATE];
    #pragma unroll
    for (int n = 0; n < NSTATE; ++n) ar[n] = g_A32[m * NSTATE + n];

    const float* Vs = (const float*)g_V4;
    float*       Hs = (float*)g_H4;
    const size_t off0 = (size_t)ch * NSTATE + m;
    const size_t step = (size_t)NCH * NSTATE;

    float h = 0.f;
    float v = Vs[off0];                                // prefetch g=0
    size_t off = off0;
    for (int g = 0; g < NSEGS; ++g) {
        float v_next = 0.f;
        if (g < NSEGS - 1) v_next = Vs[off + step];    // prefetch next (hides L2 latency)
        Hs[off] = h;                                   // entry state of segment g
        float a0 = v, a1 = 0.f, a2 = 0.f, a3 = 0.f;
        #pragma unroll
        for (int n = 0; n < NSTATE; n += 4) {
            a0 = fmaf(ar[n + 0], __shfl_sync(0xffffffffu, h, n + 0, 16), a0);
            a1 = fmaf(ar[n + 1], __shfl_sync(0xffffffffu, h, n + 1, 16), a1);
            a2 = fmaf(ar[n + 2], __shfl_sync(0xffffffffu, h, n + 2, 16), a2);
            a3 = fmaf(ar[n + 3], __shfl_sync(0xffffffffu, h, n + 3, 16), a3);
        }
        h = (a0 + a1) + (a2 + a3);
        v = v_next;
        off += step;
    }
}

// ---------------- K3: y = conv(x) + Q . H_seg.  x staged in SMEM, 1 thread/(ch,seg) --
__global__ void __launch_bounds__(256, 4) k3_fused(const float* __restrict__ x,
                                                   float* __restrict__ out) {
    __shared__ float      sx[SEG][256];     // 32 KB x tile, read once from DRAM
    __shared__ float      sc[SEG];
    __shared__ ulonglong2 sQp[SEG][4];      // Q rows as packed f32x2 pairs
    const int tid = threadIdx.x;
    if (tid < SEG) sc[tid] = g_c[tid];
    if (tid < SEG * 4) ((ulonglong2*)sQp)[tid] = ((const ulonglong2*)g_Q4)[tid];

    const int bid = blockIdx.x;             // 1024 blocks = 4 dtiles * 4 batch * 64 segs
    const int dt  = bid & 3;
    const int b   = (bid >> 2) & 3;
    const int g   = bid >> 4;
    const int d   = dt * 256 + tid;

    const size_t base = ((size_t)(b * SEQ + g * SEG)) * DMODEL + d;
    const float* xp = x + base;
    #pragma unroll
    for (int s = 0; s < SEG; ++s) sx[s][tid] = xp[(size_t)s * DMODEL];
    __syncthreads();

    // entry state H, packed into 8 f32x2 pairs
    const int ch = b * DMODEL + d;
    const float4* hp = g_H4 + ((size_t)g * NCH + ch) * 4;
    const float4 h0 = hp[0], h1 = hp[1], h2 = hp[2], h3 = hp[3];
    ull H2[8];
    H2[0] = pack2(h0.x, h0.y); H2[1] = pack2(h0.z, h0.w);
    H2[2] = pack2(h1.x, h1.y); H2[3] = pack2(h1.z, h1.w);
    H2[4] = pack2(h2.x, h2.y); H2[5] = pack2(h2.z, h2.w);
    H2[6] = pack2(h3.x, h3.y); H2[7] = pack2(h3.z, h3.w);

    float* op = out + base;

    #pragma unroll
    for (int rbase = 0; rbase < SEG; rbase += 16) {
        float acc[16];
        // acc[i] = Q[rbase+i] . H   (packed: 8 fma2 per output)
        #pragma unroll
        for (int i = 0; i < 16; ++i) {
            const ulonglong2 qa = sQp[rbase + i][0], qb = sQp[rbase + i][1];
            const ulonglong2 qc = sQp[rbase + i][2], qd = sQp[rbase + i][3];
            ull p = 0ull;
            fma2(p, qa.x, H2[0]); fma2(p, qa.y, H2[1]);
            fma2(p, qb.x, H2[2]); fma2(p, qb.y, H2[3]);
            fma2(p, qc.x, H2[4]); fma2(p, qc.y, H2[5]);
            fma2(p, qd.x, H2[6]); fma2(p, qd.y, H2[7]);
            acc[i] = unpack_add(p);
        }
        // conv: acc[i] += sum_s c[rbase+i-s] * x[s]; compile-time predicates only
        #pragma unroll
        for (int s = 0; s < SEG; ++s) {
            if (s > rbase + 15) break;
            const float xv = sx[s][tid];
            #pragma unroll
            for (int i = 0; i < 16; ++i) {
                const int k = rbase + i - s;
                if (k >= 0 && k < SEG) acc[i] = fmaf(sc[k], xv, acc[i]);
            }
        }
        #pragma unroll
        for (int i = 0; i < 16; ++i) op[(size_t)(rbase + i) * DMODEL] = acc[i];
    }
}

// ---------------- launch ----------------
extern "C" void kernel_launch(void* const* d_in, const int* in_sizes, int n_in,
                              void* d_out, int out_size) {
    const float* x = nullptr; const float* A = nullptr; const float* bv = nullptr;
    for (int i = 0; i < n_in; ++i) {
        if      (in_sizes[i] == BATCH * SEQ * DMODEL) x  = (const float*)d_in[i];
        else if (in_sizes[i] == NSTATE * NSTATE)      A  = (const float*)d_in[i];
        else if (in_sizes[i] == NSTATE)               bv = (const float*)d_in[i];
    }
    float* out = (float*)d_out;

    k0_precompute<<<1, 256>>>(A, bv);
    k1_inject<<<(NCH * NSEGS) / 256, 256>>>(x);              // 1024 blocks
    k2_prefix<<<(NCH * NSTATE) / 256, 256>>>();              // 256 blocks
    k3_fused<<<(NCH * NSEGS) / 256, 256>>>(x, out);          // 1024 blocks
}